// round 3
// baseline (speedup 1.0000x reference)
#include <cuda_runtime.h>

// Fixed problem shape (SGConv_52613349376206): B=4, N=16384, D=128, E=1048576
#define BB 4
#define NN 16384
#define DD 128
#define BN (BB * NN)   // 65536 rows

// Scratch (static __device__ arrays: allocation-free per harness rules)
__device__ float g_deg[BN];                       // 256 KB
__device__ float g_y[(size_t)BN * DD];            // 32 MB : y = (x@W)*norm[src]

// packed fp32x2 FMA (Blackwell): acc = a*b + acc on both 32-bit halves
#define FMA2(acc, a, b) \
    asm("fma.rn.f32x2 %0, %1, %2, %0;" : "+l"(acc) : "l"(a), "l"(b))

// ---------------------------------------------------------------------------
// K0: zero the output accumulator and the degree array
// ---------------------------------------------------------------------------
__global__ void zero_kernel(float4* __restrict__ out4) {
    int i = blockIdx.x * blockDim.x + threadIdx.x;
    if (i < (BN * DD / 4)) out4[i] = make_float4(0.f, 0.f, 0.f, 0.f);
    if (i < (BN / 4)) reinterpret_cast<float4*>(g_deg)[i] = make_float4(0.f, 0.f, 0.f, 0.f);
}

// ---------------------------------------------------------------------------
// K1: deg[b*N + row] += |val|   (scalar RED, 1M ops over 64K addresses)
// ---------------------------------------------------------------------------
__global__ void deg_kernel(const int* __restrict__ eb, const int* __restrict__ er,
                           const float* __restrict__ ev, int E) {
    int e = blockIdx.x * blockDim.x + threadIdx.x;
    if (e < E) atomicAdd(&g_deg[eb[e] * NN + er[e]], fabsf(ev[e]));
}

// ---------------------------------------------------------------------------
// K2: y = (x @ W) * rsqrt(deg + 1e-6)   — fp32x2 packed-FMA GEMM
// Block: 256 threads, 64 rows x 128 cols tile, K chunked by 32.
// Thread (tx,ty): cols {2tx, 2tx+1, 2tx+64, 2tx+65}, rows {ty, ty+8, ..., ty+56}
// x is stored duplicated ({v,v}) in smem so the packed A-operand is a single
// broadcast LDS.64 — no pack instructions in the inner loop.
// ---------------------------------------------------------------------------
__global__ __launch_bounds__(256) void gemm_kernel(const float* __restrict__ x,
                                                   const float* __restrict__ Wg) {
    __shared__ float2 Xs[64][32];     // 16 KB, duplicated x values
    __shared__ float  Ws[32][128];    // 16 KB
    __shared__ float  snorm[64];

    const int tid = threadIdx.x;
    const int rowBase = blockIdx.x * 64;
    if (tid < 64) snorm[tid] = rsqrtf(g_deg[rowBase + tid] + 1e-6f);

    const int tx = tid & 31;
    const int ty = tid >> 5;
    const int c0 = tx * 2;

    unsigned long long accA[8], accB[8];
#pragma unroll
    for (int i = 0; i < 8; i++) { accA[i] = 0ULL; accB[i] = 0ULL; }

    for (int kc = 0; kc < 4; kc++) {
        // load x chunk [64 rows x 32 k], duplicated
        for (int t = tid; t < 512; t += 256) {
            int r = t >> 3, q = t & 7;
            float4 xv = *reinterpret_cast<const float4*>(
                x + (size_t)(rowBase + r) * DD + kc * 32 + q * 4);
            int cc = q * 4;
            Xs[r][cc + 0] = make_float2(xv.x, xv.x);
            Xs[r][cc + 1] = make_float2(xv.y, xv.y);
            Xs[r][cc + 2] = make_float2(xv.z, xv.z);
            Xs[r][cc + 3] = make_float2(xv.w, xv.w);
        }
        // load W chunk [32 k x 128 cols]
        for (int t = tid; t < 1024; t += 256) {
            int kk = t >> 5, q = t & 31;
            *reinterpret_cast<float4*>(&Ws[kk][q * 4]) =
                *reinterpret_cast<const float4*>(Wg + (size_t)(kc * 32 + kk) * DD + q * 4);
        }
        __syncthreads();

#pragma unroll
        for (int kk = 0; kk < 32; kk++) {
            unsigned long long wA = *reinterpret_cast<const unsigned long long*>(&Ws[kk][c0]);
            unsigned long long wB = *reinterpret_cast<const unsigned long long*>(&Ws[kk][c0 + 64]);
#pragma unroll
            for (int i = 0; i < 8; i++) {
                unsigned long long xa =
                    *reinterpret_cast<const unsigned long long*>(&Xs[ty + i * 8][kk]);
                FMA2(accA[i], xa, wA);
                FMA2(accB[i], xa, wB);
            }
        }
        __syncthreads();
    }

    // epilogue: scale by norm[row], write y
#pragma unroll
    for (int i = 0; i < 8; i++) {
        int r = ty + i * 8;
        float n = snorm[r];
        float2 a = *reinterpret_cast<float2*>(&accA[i]);
        float2 b2 = *reinterpret_cast<float2*>(&accB[i]);
        float* yo = g_y + (size_t)(rowBase + r) * DD;
        *reinterpret_cast<float2*>(&yo[c0])      = make_float2(a.x * n, a.y * n);
        *reinterpret_cast<float2*>(&yo[c0 + 64]) = make_float2(b2.x * n, b2.y * n);
    }
}

// ---------------------------------------------------------------------------
// K3: SpMM — one warp per edge; lane handles 4 contiguous floats.
//     out[dst] += val * y[src]   via vector float4 atomicAdd (RED.128)
// y (32MB) and out (32MB) are both L2-resident -> LTS-bound.
// ---------------------------------------------------------------------------
__global__ void spmm_kernel(const int* __restrict__ eb, const int* __restrict__ er,
                            const int* __restrict__ ec, const float* __restrict__ ev,
                            float* __restrict__ out, int E) {
    int w = (blockIdx.x * blockDim.x + threadIdx.x) >> 5;
    if (w >= E) return;
    int lane = threadIdx.x & 31;

    int b   = __ldg(eb + w);                  // broadcast loads (1 sector each)
    int dst = b * NN + __ldg(er + w);
    int src = b * NN + __ldg(ec + w);
    float v = __ldg(ev + w);

    float4 y4 = *reinterpret_cast<const float4*>(g_y + (size_t)src * DD + lane * 4);
    float4 m  = make_float4(y4.x * v, y4.y * v, y4.z * v, y4.w * v);

    atomicAdd(reinterpret_cast<float4*>(out + (size_t)dst * DD + lane * 4), m);
}

// ---------------------------------------------------------------------------
// K4: out = relu(out * norm[row] + bias)
// ---------------------------------------------------------------------------
__global__ void epilogue_kernel(float4* __restrict__ out4, const float* __restrict__ bias) {
    int i = blockIdx.x * blockDim.x + threadIdx.x;
    if (i >= BN * DD / 4) return;
    int row = i >> 5;          // 32 float4 per row of 128
    int c4  = i & 31;
    float n = rsqrtf(g_deg[row] + 1e-6f);
    float4 v  = out4[i];
    float4 bv = *reinterpret_cast<const float4*>(bias + c4 * 4);
    v.x = fmaxf(fmaf(v.x, n, bv.x), 0.f);
    v.y = fmaxf(fmaf(v.y, n, bv.y), 0.f);
    v.z = fmaxf(fmaf(v.z, n, bv.z), 0.f);
    v.w = fmaxf(fmaf(v.w, n, bv.w), 0.f);
    out4[i] = v;
}

// ---------------------------------------------------------------------------
// launch — inputs per metadata order:
// x, W, b, edge_b, edge_row, edge_col, edge_vals, k(unused)
// ---------------------------------------------------------------------------
extern "C" void kernel_launch(void* const* d_in, const int* in_sizes, int n_in,
                              void* d_out, int out_size) {
    const float* x    = (const float*)d_in[0];
    const float* Wg   = (const float*)d_in[1];
    const float* bias = (const float*)d_in[2];
    const int*   eb   = (const int*)d_in[3];
    const int*   er   = (const int*)d_in[4];
    const int*   ec   = (const int*)d_in[5];
    const float* ev   = (const float*)d_in[6];
    const int E = in_sizes[3];
    float* out = (float*)d_out;

    zero_kernel<<<(BN * DD / 4 + 255) / 256, 256>>>((float4*)out);
    deg_kernel<<<(E + 255) / 256, 256>>>(eb, er, ev, E);
    gemm_kernel<<<BN / 64, 256>>>(x, Wg);
    spmm_kernel<<<((size_t)E * 32 + 255) / 256, 256>>>(eb, er, ec, ev, out, E);
    epilogue_kernel<<<(BN * DD / 4) / 256, 256>>>((float4*)out, bias);
}